// round 12
// baseline (speedup 1.0000x reference)
#include <cuda_runtime.h>
#include <cstdint>

// FilterTransform: cascaded biquads (fixed HP + random coeffs) over time,
// x[4096,16000] and n[4096,16000] -> out [8192,16000].
//
// R10 (from R9 @174.8us): per-warp serial issue is the wall (2660 cyc/tile;
// fma rt-floor 1536). Replace the 14 warp-wide cp.async (rt8 = 112 issue cyc)
// with lane-0 cp.async.bulk G2S completing on an mbarrier (expect_tx), and a
// single parity wait. Stores remain bulk S2G; smem reuse gated by
// bulk.wait_group.read 1 ordered same-thread with the refill issue.

static constexpr int T_LEN   = 16000;
static constexpr int HALF    = 4096;
static constexpr int SEG     = 32;                  // float4 per row per tile (512B)
static constexpr int NTILES  = (T_LEN / 4) / SEG;   // 125
static constexpr int ROWS    = 14;                  // rows per block (1 warp)
static constexpr int XBLOCKS = (HALF + ROWS - 1) / ROWS;  // 293
static constexpr int PAD     = 1;                   // conflict-free LDS; 512B data
                                                    // region per row stays contiguous
static constexpr int NBUF    = 4;
static constexpr int ROW_BYTES = SEG * 16;          // 512

__device__ __forceinline__ void bulk_g2s(uint32_t sdst, const void* gsrc,
                                         uint32_t bytes, uint32_t mbar) {
    asm volatile(
        "cp.async.bulk.shared::cta.global.mbarrier::complete_tx::bytes [%0], [%1], %2, [%3];"
        :: "r"(sdst), "l"(gsrc), "r"(bytes), "r"(mbar) : "memory");
}
__device__ __forceinline__ void bulk_s2g(void* gdst, uint32_t ssrc, uint32_t bytes) {
    asm volatile("cp.async.bulk.global.shared::cta.bulk_group [%0], [%1], %2;"
                 :: "l"(gdst), "r"(ssrc), "r"(bytes) : "memory");
}
__device__ __forceinline__ void bulk_commit() {
    asm volatile("cp.async.bulk.commit_group;" ::: "memory");
}
__device__ __forceinline__ void bulk_wait_read1() {
    asm volatile("cp.async.bulk.wait_group.read 1;" ::: "memory");
}
__device__ __forceinline__ void bulk_wait_all() {
    asm volatile("cp.async.bulk.wait_group 0;" ::: "memory");
}
__device__ __forceinline__ void fence_async_shared() {
    asm volatile("fence.proxy.async.shared::cta;" ::: "memory");
}
__device__ __forceinline__ void mbar_init(uint32_t mbar, uint32_t count) {
    asm volatile("mbarrier.init.shared.b64 [%0], %1;" :: "r"(mbar), "r"(count) : "memory");
}
__device__ __forceinline__ void mbar_expect_tx(uint32_t mbar, uint32_t bytes) {
    asm volatile("mbarrier.arrive.expect_tx.shared.b64 _, [%0], %1;"
                 :: "r"(mbar), "r"(bytes) : "memory");
}
__device__ __forceinline__ void mbar_wait(uint32_t mbar, uint32_t parity) {
    asm volatile(
        "{\n\t"
        ".reg .pred P1;\n\t"
        "WAIT_LOOP_%=:\n\t"
        "mbarrier.try_wait.parity.acquire.cta.shared::cta.b64 P1, [%0], %1, 0x989680;\n\t"
        "@P1 bra.uni WAIT_DONE_%=;\n\t"
        "bra.uni WAIT_LOOP_%=;\n\t"
        "WAIT_DONE_%=:\n\t"
        "}"
        :: "r"(mbar), "r"(parity) : "memory");
}
__device__ __forceinline__ float fma_imm1(float a, float c) {
    // a*1.0 + c as FFMA-imm (rt 1); bit-identical to a + c.
    float d;
    asm("fma.rn.f32 %0, %1, 0f3F800000, %2;" : "=f"(d) : "f"(a), "f"(c));
    return d;
}

__global__ __launch_bounds__(32)
void biquad_cascade_kernel(const float* __restrict__ x,
                           const float* __restrict__ n,
                           const float* __restrict__ a_x,
                           const float* __restrict__ b_x,
                           const float* __restrict__ a_n,
                           const float* __restrict__ b_n,
                           float* __restrict__ out)
{
    __shared__ float4 tile[NBUF][ROWS][SEG + PAD];
    __shared__ __align__(8) unsigned long long full_mbar[NBUF];

    const int lane = threadIdx.x;
    const bool is_x = (blockIdx.x < XBLOCKS);
    const int bi = is_x ? blockIdx.x : blockIdx.x - XBLOCKS;
    const int rowbase = bi * ROWS;
    const int nrows = (HALF - rowbase) < ROWS ? (HALF - rowbase) : ROWS;

    const float* inbase = is_x ? (x + (size_t)rowbase * T_LEN)
                               : (n + (size_t)rowbase * T_LEN);
    float* outbase = out + (size_t)(is_x ? rowbase : rowbase + HALF) * T_LEN;

    float b0, b1, na0, na1;
    if (is_x) { na0 = -a_x[0]; na1 = -a_x[1]; b0 = b_x[0]; b1 = b_x[1]; }
    else      { na0 = -a_n[0]; na1 = -a_n[1]; b0 = b_n[0]; b1 = b_n[1]; }

    // Stage 1 (HP) DF2T state; stage 2 DF-I histories.
    float m0 = 0.f, m1 = 0.f;
    float u1 = 0.f, u2 = 0.f, v1 = 0.f, v2 = 0.f;

    const bool leader = (lane == 0);

    uint32_t mb[NBUF];
    #pragma unroll
    for (int b = 0; b < NBUF; b++)
        mb[b] = (uint32_t)__cvta_generic_to_shared(&full_mbar[b]);

    if (leader) {
        #pragma unroll
        for (int b = 0; b < NBUF; b++) mbar_init(mb[b], 1);
    }
    __syncwarp();

    // lane-0 bulk G2S load of one tile (512B per row), completing on mbarrier.
    auto load_tile = [&](int g) {
        const int buf = g & (NBUF - 1);
        mbar_expect_tx(mb[buf], (uint32_t)(nrows * ROW_BYTES));
        const float* src = inbase + (size_t)g * (SEG * 4);
        for (int i = 0; i < nrows; i++) {
            uint32_t sdst = (uint32_t)__cvta_generic_to_shared(&tile[buf][i][0]);
            bulk_g2s(sdst, src + (size_t)i * T_LEN, ROW_BYTES, mb[buf]);
        }
    };

    if (leader) { load_tile(0); load_tile(1); load_tile(2); }
    __syncwarp();

    const bool active = (lane < nrows);

    for (int g = 0; g < NTILES; g++) {
        const int buf = g & (NBUF - 1);

        mbar_wait(mb[buf], (uint32_t)((g >> 2) & 1));   // tile g landed

        if (active) {
            float4* myrow = &tile[buf][lane][0];
            float4 nxt = myrow[0];
            #pragma unroll 8
            for (int j = 0; j < SEG; j++) {
                float4 vin = nxt;
                if (j + 1 < SEG) nxt = myrow[j + 1];   // rolling LDS prefetch
                float xs[4] = {vin.x, vin.y, vin.z, vin.w};
                float ys[4];
                #pragma unroll
                for (int k = 0; k < 4; k++) {
                    const float xv = xs[k];
                    // Stage 1: exact DF2T high-pass (all three FFMA-imm rt1)
                    const float y1 = fma_imm1(xv, m0);
                    m0 = fmaf(1.99599f, y1, fmaf(-2.0f, xv, m1));
                    m1 = fmaf(-0.996f, y1, xv);
                    // Stage 2: DF-I with runtime coeffs (well-damped poles)
                    float s = fmaf(b0, u1, y1);
                    s = fmaf(b1, u2, s);
                    s = fmaf(na1, v2, s);
                    const float v = fmaf(na0, v1, s);
                    u2 = u1; u1 = y1;
                    v2 = v1; v1 = v;
                    ys[k] = v;
                }
                myrow[j] = make_float4(ys[0], ys[1], ys[2], ys[3]);
            }
        }
        __syncwarp();   // all lanes' STS done before leader's fence + bulk reads

        if (leader) {
            fence_async_shared();          // order generic STS before async reads
            float* dst = outbase + (size_t)g * (SEG * 4);
            for (int i = 0; i < nrows; i++) {
                uint32_t ssrc = (uint32_t)__cvta_generic_to_shared(&tile[buf][i][0]);
                bulk_s2g(dst + (size_t)i * T_LEN, ssrc, ROW_BYTES);
            }
            bulk_commit();
            bulk_wait_read1();             // tile g-1's smem reads drained
            if (g + 3 < NTILES) load_tile(g + 3);   // refill buf (g-1)%4
        }
        // No trailing sync needed: consumers gate on the next full-mbarrier.
    }

    if (leader) bulk_wait_all();           // all bulk stores complete before exit
}

extern "C" void kernel_launch(void* const* d_in, const int* in_sizes, int n_in,
                              void* d_out, int out_size)
{
    const float* x   = (const float*)d_in[0];
    const float* n   = (const float*)d_in[1];
    const float* a_x = (const float*)d_in[2];
    const float* b_x = (const float*)d_in[3];
    const float* a_n = (const float*)d_in[4];
    const float* b_n = (const float*)d_in[5];
    float* out = (float*)d_out;

    biquad_cascade_kernel<<<2 * XBLOCKS, 32>>>(x, n, a_x, b_x, a_n, b_n, out);
}

// round 13
// speedup vs baseline: 1.0537x; 1.0537x over previous
#include <cuda_runtime.h>
#include <cstdint>

// FilterTransform: cascaded biquads (fixed HP + random coeffs) over time,
// x[4096,16000] and n[4096,16000] -> out [8192,16000].
//
// R10 (from R9 @174.8us): per-warp serial issue is the wall (2660 cyc/tile;
// fma rt-floor 1536). Replace the 14 warp-wide cp.async (rt8 = 112 issue cyc)
// with lane-0 cp.async.bulk G2S completing on an mbarrier (expect_tx), and a
// single parity wait. Stores remain bulk S2G; smem reuse gated by
// bulk.wait_group.read 1 ordered same-thread with the refill issue.

static constexpr int T_LEN   = 16000;
static constexpr int HALF    = 4096;
static constexpr int SEG     = 32;                  // float4 per row per tile (512B)
static constexpr int NTILES  = (T_LEN / 4) / SEG;   // 125
static constexpr int ROWS    = 14;                  // rows per block (1 warp)
static constexpr int XBLOCKS = (HALF + ROWS - 1) / ROWS;  // 293
static constexpr int PAD     = 1;                   // conflict-free LDS; 512B data
                                                    // region per row stays contiguous
static constexpr int NBUF    = 4;
static constexpr int ROW_BYTES = SEG * 16;          // 512

__device__ __forceinline__ void bulk_g2s(uint32_t sdst, const void* gsrc,
                                         uint32_t bytes, uint32_t mbar) {
    asm volatile(
        "cp.async.bulk.shared::cta.global.mbarrier::complete_tx::bytes [%0], [%1], %2, [%3];"
        :: "r"(sdst), "l"(gsrc), "r"(bytes), "r"(mbar) : "memory");
}
__device__ __forceinline__ void bulk_s2g(void* gdst, uint32_t ssrc, uint32_t bytes) {
    asm volatile("cp.async.bulk.global.shared::cta.bulk_group [%0], [%1], %2;"
                 :: "l"(gdst), "r"(ssrc), "r"(bytes) : "memory");
}
__device__ __forceinline__ void bulk_commit() {
    asm volatile("cp.async.bulk.commit_group;" ::: "memory");
}
__device__ __forceinline__ void bulk_wait_read1() {
    asm volatile("cp.async.bulk.wait_group.read 1;" ::: "memory");
}
__device__ __forceinline__ void bulk_wait_all() {
    asm volatile("cp.async.bulk.wait_group 0;" ::: "memory");
}
__device__ __forceinline__ void fence_async_shared() {
    asm volatile("fence.proxy.async.shared::cta;" ::: "memory");
}
__device__ __forceinline__ void mbar_init(uint32_t mbar, uint32_t count) {
    asm volatile("mbarrier.init.shared.b64 [%0], %1;" :: "r"(mbar), "r"(count) : "memory");
}
__device__ __forceinline__ void mbar_expect_tx(uint32_t mbar, uint32_t bytes) {
    asm volatile("mbarrier.arrive.expect_tx.shared.b64 _, [%0], %1;"
                 :: "r"(mbar), "r"(bytes) : "memory");
}
__device__ __forceinline__ void mbar_wait(uint32_t mbar, uint32_t parity) {
    asm volatile(
        "{\n\t"
        ".reg .pred P1;\n\t"
        "WAIT_LOOP_%=:\n\t"
        "mbarrier.try_wait.parity.acquire.cta.shared::cta.b64 P1, [%0], %1, 0x989680;\n\t"
        "@P1 bra.uni WAIT_DONE_%=;\n\t"
        "bra.uni WAIT_LOOP_%=;\n\t"
        "WAIT_DONE_%=:\n\t"
        "}"
        :: "r"(mbar), "r"(parity) : "memory");
}
__device__ __forceinline__ float fma_imm1(float a, float c) {
    // a*1.0 + c as FFMA-imm (rt 1); bit-identical to a + c.
    float d;
    asm("fma.rn.f32 %0, %1, 0f3F800000, %2;" : "=f"(d) : "f"(a), "f"(c));
    return d;
}

__global__ __launch_bounds__(32)
void biquad_cascade_kernel(const float* __restrict__ x,
                           const float* __restrict__ n,
                           const float* __restrict__ a_x,
                           const float* __restrict__ b_x,
                           const float* __restrict__ a_n,
                           const float* __restrict__ b_n,
                           float* __restrict__ out)
{
    __shared__ float4 tile[NBUF][ROWS][SEG + PAD];
    __shared__ __align__(8) unsigned long long full_mbar[NBUF];

    const int lane = threadIdx.x;
    const bool is_x = (blockIdx.x < XBLOCKS);
    const int bi = is_x ? blockIdx.x : blockIdx.x - XBLOCKS;
    const int rowbase = bi * ROWS;
    const int nrows = (HALF - rowbase) < ROWS ? (HALF - rowbase) : ROWS;

    const float* inbase = is_x ? (x + (size_t)rowbase * T_LEN)
                               : (n + (size_t)rowbase * T_LEN);
    float* outbase = out + (size_t)(is_x ? rowbase : rowbase + HALF) * T_LEN;

    float b0, b1, na0, na1;
    if (is_x) { na0 = -a_x[0]; na1 = -a_x[1]; b0 = b_x[0]; b1 = b_x[1]; }
    else      { na0 = -a_n[0]; na1 = -a_n[1]; b0 = b_n[0]; b1 = b_n[1]; }

    // Stage 1 (HP) DF2T state; stage 2 DF-I histories.
    float m0 = 0.f, m1 = 0.f;
    float u1 = 0.f, u2 = 0.f, v1 = 0.f, v2 = 0.f;

    const bool leader = (lane == 0);

    uint32_t mb[NBUF];
    #pragma unroll
    for (int b = 0; b < NBUF; b++)
        mb[b] = (uint32_t)__cvta_generic_to_shared(&full_mbar[b]);

    if (leader) {
        #pragma unroll
        for (int b = 0; b < NBUF; b++) mbar_init(mb[b], 1);
    }
    __syncwarp();

    // lane-0 bulk G2S load of one tile (512B per row), completing on mbarrier.
    auto load_tile = [&](int g) {
        const int buf = g & (NBUF - 1);
        mbar_expect_tx(mb[buf], (uint32_t)(nrows * ROW_BYTES));
        const float* src = inbase + (size_t)g * (SEG * 4);
        for (int i = 0; i < nrows; i++) {
            uint32_t sdst = (uint32_t)__cvta_generic_to_shared(&tile[buf][i][0]);
            bulk_g2s(sdst, src + (size_t)i * T_LEN, ROW_BYTES, mb[buf]);
        }
    };

    if (leader) { load_tile(0); load_tile(1); load_tile(2); }
    __syncwarp();

    const bool active = (lane < nrows);

    for (int g = 0; g < NTILES; g++) {
        const int buf = g & (NBUF - 1);

        mbar_wait(mb[buf], (uint32_t)((g >> 2) & 1));   // tile g landed

        if (active) {
            float4* myrow = &tile[buf][lane][0];
            float4 nxt = myrow[0];
            #pragma unroll 8
            for (int j = 0; j < SEG; j++) {
                float4 vin = nxt;
                if (j + 1 < SEG) nxt = myrow[j + 1];   // rolling LDS prefetch
                float xs[4] = {vin.x, vin.y, vin.z, vin.w};
                float ys[4];
                #pragma unroll
                for (int k = 0; k < 4; k++) {
                    const float xv = xs[k];
                    // Stage 1: exact DF2T high-pass (all three FFMA-imm rt1)
                    const float y1 = fma_imm1(xv, m0);
                    m0 = fmaf(1.99599f, y1, fmaf(-2.0f, xv, m1));
                    m1 = fmaf(-0.996f, y1, xv);
                    // Stage 2: DF-I with runtime coeffs (well-damped poles)
                    float s = fmaf(b0, u1, y1);
                    s = fmaf(b1, u2, s);
                    s = fmaf(na1, v2, s);
                    const float v = fmaf(na0, v1, s);
                    u2 = u1; u1 = y1;
                    v2 = v1; v1 = v;
                    ys[k] = v;
                }
                myrow[j] = make_float4(ys[0], ys[1], ys[2], ys[3]);
            }
        }
        __syncwarp();   // all lanes' STS done before leader's fence + bulk reads

        if (leader) {
            fence_async_shared();          // order generic STS before async reads
            float* dst = outbase + (size_t)g * (SEG * 4);
            for (int i = 0; i < nrows; i++) {
                uint32_t ssrc = (uint32_t)__cvta_generic_to_shared(&tile[buf][i][0]);
                bulk_s2g(dst + (size_t)i * T_LEN, ssrc, ROW_BYTES);
            }
            bulk_commit();
            bulk_wait_read1();             // tile g-1's smem reads drained
            if (g + 3 < NTILES) load_tile(g + 3);   // refill buf (g-1)%4
        }
        // No trailing sync needed: consumers gate on the next full-mbarrier.
    }

    if (leader) bulk_wait_all();           // all bulk stores complete before exit
}

extern "C" void kernel_launch(void* const* d_in, const int* in_sizes, int n_in,
                              void* d_out, int out_size)
{
    const float* x   = (const float*)d_in[0];
    const float* n   = (const float*)d_in[1];
    const float* a_x = (const float*)d_in[2];
    const float* b_x = (const float*)d_in[3];
    const float* a_n = (const float*)d_in[4];
    const float* b_n = (const float*)d_in[5];
    float* out = (float*)d_out;

    biquad_cascade_kernel<<<2 * XBLOCKS, 32>>>(x, n, a_x, b_x, a_n, b_n, out);
}

// round 14
// speedup vs baseline: 1.1964x; 1.1354x over previous
#include <cuda_runtime.h>
#include <cstdint>

// FilterTransform: cascaded biquads (fixed HP + random coeffs) over time,
// x[4096,16000] and n[4096,16000] -> out [8192,16000].
//
// R11 (from R9 best @174.8us; R10 mbarrier loads regressed -> reverted):
// the ~1100 cyc/tile of memory-phase serialization is folded INTO the
// compute loop: the 14 warp-wide cp.async for tile g+3 issue one-per-
// unrolled-iteration inside the 32-step sample loop (free issue slots:
// compute uses ~8 of 12 fma-pipe rt-cyc/sample). All 32 lanes stay
// converged (lanes >= 14 compute on a scratch smem row, never stored).
// Ring of 5 buffers so the refill target's bulk-store reads are already
// drained (bulk_wait_read1 at end of previous tile + top-of-loop sync).

static constexpr int T_LEN   = 16000;
static constexpr int HALF    = 4096;
static constexpr int SEG     = 32;                  // float4 per row per tile (512B)
static constexpr int NTILES  = (T_LEN / 4) / SEG;   // 125
static constexpr int ROWS    = 14;                  // real rows per block (1 warp)
static constexpr int XBLOCKS = (HALF + ROWS - 1) / ROWS;  // 293
static constexpr int PAD     = 1;                   // 528B row stride: conflict-light LDS
static constexpr int NBUF    = 5;
static constexpr int SROWS   = ROWS + 1;            // +1 scratch row for lanes 14..31
static constexpr int ROW_BYTES = SEG * 16;          // 512

__device__ __forceinline__ void cp_async16(uint32_t saddr, const void* gptr) {
    asm volatile("cp.async.cg.shared.global [%0], [%1], 16;"
                 :: "r"(saddr), "l"(gptr) : "memory");
}
__device__ __forceinline__ void cp_commit() {
    asm volatile("cp.async.commit_group;" ::: "memory");
}
__device__ __forceinline__ void cp_wait2() {
    asm volatile("cp.async.wait_group 2;" ::: "memory");
}
__device__ __forceinline__ void bulk_s2g(void* gdst, uint32_t ssrc, uint32_t bytes) {
    asm volatile("cp.async.bulk.global.shared::cta.bulk_group [%0], [%1], %2;"
                 :: "l"(gdst), "r"(ssrc), "r"(bytes) : "memory");
}
__device__ __forceinline__ void bulk_commit() {
    asm volatile("cp.async.bulk.commit_group;" ::: "memory");
}
__device__ __forceinline__ void bulk_wait_read1() {
    asm volatile("cp.async.bulk.wait_group.read 1;" ::: "memory");
}
__device__ __forceinline__ void bulk_wait_all() {
    asm volatile("cp.async.bulk.wait_group 0;" ::: "memory");
}
__device__ __forceinline__ void fence_async_shared() {
    asm volatile("fence.proxy.async.shared::cta;" ::: "memory");
}
__device__ __forceinline__ float fma_imm1(float a, float c) {
    // a*1.0 + c as FFMA-imm (rt 1); bit-identical to a + c.
    float d;
    asm("fma.rn.f32 %0, %1, 0f3F800000, %2;" : "=f"(d) : "f"(a), "f"(c));
    return d;
}

__global__ __launch_bounds__(32)
void biquad_cascade_kernel(const float* __restrict__ x,
                           const float* __restrict__ n,
                           const float* __restrict__ a_x,
                           const float* __restrict__ b_x,
                           const float* __restrict__ a_n,
                           const float* __restrict__ b_n,
                           float* __restrict__ out)
{
    __shared__ float4 tile[NBUF][SROWS][SEG + PAD];

    const int lane = threadIdx.x;
    const bool is_x = (blockIdx.x < XBLOCKS);
    const int bi = is_x ? blockIdx.x : blockIdx.x - XBLOCKS;
    const int rowbase = bi * ROWS;
    const int nrows = (HALF - rowbase) < ROWS ? (HALF - rowbase) : ROWS;

    const float* inbase = is_x ? (x + (size_t)rowbase * T_LEN)
                               : (n + (size_t)rowbase * T_LEN);
    float* outbase = out + (size_t)(is_x ? rowbase : rowbase + HALF) * T_LEN;

    float b0, b1, na0, na1;
    if (is_x) { na0 = -a_x[0]; na1 = -a_x[1]; b0 = b_x[0]; b1 = b_x[1]; }
    else      { na0 = -a_n[0]; na1 = -a_n[1]; b0 = b_n[0]; b1 = b_n[1]; }

    // Stage 1 (HP) DF2T state; stage 2 DF-I histories.
    float m0 = 0.f, m1 = 0.f;
    float u1 = 0.f, u2 = 0.f, v1 = 0.f, v2 = 0.f;

    const bool leader = (lane == 0);
    // Lanes >= ROWS compute on scratch row (broadcast LDS, collapsed STS).
    const int myRowIdx = (lane < ROWS) ? lane : ROWS;

    // Warp-wide prologue load of one tile (row-clamped for partial blocks).
    auto issue_tile = [&](int g, int slot) {
        const float* src = inbase + (size_t)g * (SEG * 4) + lane * 4;
        #pragma unroll
        for (int i = 0; i < ROWS; i++) {
            const int rr = (i < nrows) ? i : (nrows - 1);
            uint32_t saddr = (uint32_t)__cvta_generic_to_shared(&tile[slot][i][lane]);
            cp_async16(saddr, src + (size_t)rr * T_LEN);
        }
    };

    issue_tile(0, 0); cp_commit();
    issue_tile(1, 1); cp_commit();
    issue_tile(2, 2); cp_commit();

    int slot = 0;        // g % NBUF
    int refill = 3;      // (g+3) % NBUF

    for (int g = 0; g < NTILES; g++) {
        cp_wait2();          // tile g landed (<=2 newer load groups pending)
        __syncwarp();        // cross-lane smem visibility; also orders refill
                             // cp.async after leader's bulk_wait_read1 (g-1)

        // Refill source: tile g+3 (clamped at the tail; harmless re-read).
        const int g3 = (g + 3 < NTILES) ? (g + 3) : (NTILES - 1);
        const float* rsrc = inbase + (size_t)g3 * (SEG * 4) + lane * 4;
        uint32_t rbase = (uint32_t)__cvta_generic_to_shared(&tile[refill][0][lane]);

        float4* myrow = &tile[slot][myRowIdx][0];
        float4 vA = myrow[0];
        float4 vB = myrow[1];

        #pragma unroll
        for (int j = 0; j < SEG; j++) {
            float4 vin = vA;
            vA = vB;
            if (j + 2 < SEG) vB = myrow[j + 2];      // LDS prefetch distance 2

            if (j < ROWS) {                          // compile-time predicate:
                const int rr = (j < nrows) ? j : (nrows - 1);
                cp_async16(rbase + (uint32_t)j * (SROWS ? (SEG + PAD) * 16 : 0),
                           rsrc + (size_t)rr * T_LEN);
            }

            float xs[4] = {vin.x, vin.y, vin.z, vin.w};
            float ys[4];
            #pragma unroll
            for (int k = 0; k < 4; k++) {
                const float xv = xs[k];
                // Stage 1: exact DF2T high-pass (all FFMA-imm rt1)
                const float y1 = fma_imm1(xv, m0);
                m0 = fmaf(1.99599f, y1, fmaf(-2.0f, xv, m1));
                m1 = fmaf(-0.996f, y1, xv);
                // Stage 2: DF-I with runtime coeffs (well-damped poles)
                float s = fmaf(b0, u1, y1);
                s = fmaf(b1, u2, s);
                s = fmaf(na1, v2, s);
                const float v = fmaf(na0, v1, s);
                u2 = u1; u1 = y1;
                v2 = v1; v1 = v;
                ys[k] = v;
            }
            myrow[j] = make_float4(ys[0], ys[1], ys[2], ys[3]);
        }
        cp_commit();         // exactly one load group per tile

        __syncwarp();        // all lanes' STS done before leader's async reads

        if (leader) {
            fence_async_shared();            // order generic STS before bulk reads
            float* dst = outbase + (size_t)g * (SEG * 4);
            for (int i = 0; i < nrows; i++) {
                uint32_t ssrc = (uint32_t)__cvta_generic_to_shared(&tile[slot][i][0]);
                bulk_s2g(dst + (size_t)i * T_LEN, ssrc, ROW_BYTES);
            }
            bulk_commit();
            bulk_wait_read1();               // tile g-1's smem reads drained
        }

        slot   = (slot + 1 == NBUF)   ? 0 : slot + 1;
        refill = (refill + 1 == NBUF) ? 0 : refill + 1;
    }

    if (leader) bulk_wait_all();             // all bulk stores complete before exit
}

extern "C" void kernel_launch(void* const* d_in, const int* in_sizes, int n_in,
                              void* d_out, int out_size)
{
    const float* x   = (const float*)d_in[0];
    const float* n   = (const float*)d_in[1];
    const float* a_x = (const float*)d_in[2];
    const float* b_x = (const float*)d_in[3];
    const float* a_n = (const float*)d_in[4];
    const float* b_n = (const float*)d_in[5];
    float* out = (float*)d_out;

    biquad_cascade_kernel<<<2 * XBLOCKS, 32>>>(x, n, a_x, b_x, a_n, b_n, out);
}

// round 15
// speedup vs baseline: 1.2014x; 1.0042x over previous
#include <cuda_runtime.h>
#include <cstdint>

// FilterTransform: cascaded biquads (fixed HP + random coeffs) over time,
// x[4096,16000] and n[4096,16000] -> out [8192,16000].
//
// R12 (from R11 @169.6us): bulk stores of tile g-1 are now ALSO issued
// inside tile g's compute loop (lane-0-predicated, j=16..29), removing the
// end-of-tile serial store section. Ring = 6 buffers: refill target at
// tile g is tile g-3's slot, whose store group (committed end of g-2) is
// second-newest -> bulk_wait_read1 at top of tile g guarantees its smem
// reads drained before the refill cp.asyncs (ordered via syncwarp).

static constexpr int T_LEN   = 16000;
static constexpr int HALF    = 4096;
static constexpr int SEG     = 32;                  // float4 per row per tile (512B)
static constexpr int NTILES  = (T_LEN / 4) / SEG;   // 125
static constexpr int ROWS    = 14;                  // real rows per block (1 warp)
static constexpr int XBLOCKS = (HALF + ROWS - 1) / ROWS;  // 293
static constexpr int PAD     = 1;
static constexpr int NBUF    = 6;
static constexpr int SROWS   = ROWS + 1;            // +1 scratch row (lanes 14..31)
static constexpr int ROW_BYTES = SEG * 16;          // 512

__device__ __forceinline__ void cp_async16(uint32_t saddr, const void* gptr) {
    asm volatile("cp.async.cg.shared.global [%0], [%1], 16;"
                 :: "r"(saddr), "l"(gptr) : "memory");
}
__device__ __forceinline__ void cp_commit() {
    asm volatile("cp.async.commit_group;" ::: "memory");
}
__device__ __forceinline__ void cp_wait2() {
    asm volatile("cp.async.wait_group 2;" ::: "memory");
}
__device__ __forceinline__ void bulk_s2g(void* gdst, uint32_t ssrc, uint32_t bytes) {
    asm volatile("cp.async.bulk.global.shared::cta.bulk_group [%0], [%1], %2;"
                 :: "l"(gdst), "r"(ssrc), "r"(bytes) : "memory");
}
__device__ __forceinline__ void bulk_commit() {
    asm volatile("cp.async.bulk.commit_group;" ::: "memory");
}
__device__ __forceinline__ void bulk_wait_read1() {
    asm volatile("cp.async.bulk.wait_group.read 1;" ::: "memory");
}
__device__ __forceinline__ void bulk_wait_all() {
    asm volatile("cp.async.bulk.wait_group 0;" ::: "memory");
}
__device__ __forceinline__ void fence_async_shared() {
    asm volatile("fence.proxy.async.shared::cta;" ::: "memory");
}
__device__ __forceinline__ float fma_imm1(float a, float c) {
    // a*1.0 + c as FFMA-imm (rt 1); bit-identical to a + c.
    float d;
    asm("fma.rn.f32 %0, %1, 0f3F800000, %2;" : "=f"(d) : "f"(a), "f"(c));
    return d;
}

__global__ __launch_bounds__(32)
void biquad_cascade_kernel(const float* __restrict__ x,
                           const float* __restrict__ n,
                           const float* __restrict__ a_x,
                           const float* __restrict__ b_x,
                           const float* __restrict__ a_n,
                           const float* __restrict__ b_n,
                           float* __restrict__ out)
{
    __shared__ float4 tile[NBUF][SROWS][SEG + PAD];

    const int lane = threadIdx.x;
    const bool is_x = (blockIdx.x < XBLOCKS);
    const int bi = is_x ? blockIdx.x : blockIdx.x - XBLOCKS;
    const int rowbase = bi * ROWS;
    const int nrows = (HALF - rowbase) < ROWS ? (HALF - rowbase) : ROWS;

    const float* inbase = is_x ? (x + (size_t)rowbase * T_LEN)
                               : (n + (size_t)rowbase * T_LEN);
    float* outbase = out + (size_t)(is_x ? rowbase : rowbase + HALF) * T_LEN;

    float b0, b1, na0, na1;
    if (is_x) { na0 = -a_x[0]; na1 = -a_x[1]; b0 = b_x[0]; b1 = b_x[1]; }
    else      { na0 = -a_n[0]; na1 = -a_n[1]; b0 = b_n[0]; b1 = b_n[1]; }

    // Stage 1 (HP) DF2T state; stage 2 DF-I histories.
    float m0 = 0.f, m1 = 0.f;
    float u1 = 0.f, u2 = 0.f, v1 = 0.f, v2 = 0.f;

    const bool leader = (lane == 0);
    const int myRowIdx = (lane < ROWS) ? lane : ROWS;   // scratch row for hi lanes

    auto issue_tile = [&](int g, int slot) {
        const float* src = inbase + (size_t)g * (SEG * 4) + lane * 4;
        #pragma unroll
        for (int i = 0; i < ROWS; i++) {
            const int rr = (i < nrows) ? i : (nrows - 1);
            uint32_t saddr = (uint32_t)__cvta_generic_to_shared(&tile[slot][i][lane]);
            cp_async16(saddr, src + (size_t)rr * T_LEN);
        }
    };

    issue_tile(0, 0); cp_commit();
    issue_tile(1, 1); cp_commit();
    issue_tile(2, 2); cp_commit();

    int slot  = 0;                         // g % NBUF
    int sslot = NBUF - 1;                  // (g-1) % NBUF  (store slot)
    int rslot = 3;                         // (g+3) % NBUF  (refill slot)

    for (int g = 0; g < NTILES; g++) {
        cp_wait2();              // tile g's loads landed (<=2 newer groups pending)
        if (leader) bulk_wait_read1();   // refill target (tile g-3 slot) reads drained
        __syncwarp();            // publish STS of tile g-1 + leader's wait to all
        if (leader) fence_async_shared();   // order generic STS before async reads

        const bool do_refill = (g + 3 < NTILES);
        const bool do_store  = (g > 0);

        const float* rsrc = inbase + (size_t)(do_refill ? (g + 3) : 0) * (SEG * 4)
                            + lane * 4;
        uint32_t rbase = (uint32_t)__cvta_generic_to_shared(&tile[rslot][0][lane]);
        float* dst_prev = outbase + (size_t)(g - 1) * (SEG * 4);
        uint32_t sbase = (uint32_t)__cvta_generic_to_shared(&tile[sslot][0][0]);

        float4* myrow = &tile[slot][myRowIdx][0];
        float4 vA = myrow[0];
        float4 vB = myrow[1];

        #pragma unroll
        for (int j = 0; j < SEG; j++) {
            float4 vin = vA;
            vA = vB;
            if (j + 2 < SEG) vB = myrow[j + 2];        // LDS prefetch distance 2

            if (j < ROWS) {                            // refill tile g+3 (all lanes)
                const int rr = (j < nrows) ? j : (nrows - 1);
                if (do_refill)
                    cp_async16(rbase + (uint32_t)(j * (SEG + PAD) * 16),
                               rsrc + (size_t)rr * T_LEN);
            } else if (j >= 16 && j < 16 + ROWS) {     // store tile g-1 (lane 0)
                const int i = j - 16;
                if (do_store && leader && i < nrows)
                    bulk_s2g(dst_prev + (size_t)i * T_LEN,
                             sbase + (uint32_t)(i * (SEG + PAD) * 16), ROW_BYTES);
            }

            float xs[4] = {vin.x, vin.y, vin.z, vin.w};
            float ys[4];
            #pragma unroll
            for (int k = 0; k < 4; k++) {
                const float xv = xs[k];
                // Stage 1: exact DF2T high-pass (all FFMA-imm rt1)
                const float y1 = fma_imm1(xv, m0);
                m0 = fmaf(1.99599f, y1, fmaf(-2.0f, xv, m1));
                m1 = fmaf(-0.996f, y1, xv);
                // Stage 2: DF-I with runtime coeffs (well-damped poles)
                float s = fmaf(b0, u1, y1);
                s = fmaf(b1, u2, s);
                s = fmaf(na1, v2, s);
                const float v = fmaf(na0, v1, s);
                u2 = u1; u1 = y1;
                v2 = v1; v1 = v;
                ys[k] = v;
            }
            myrow[j] = make_float4(ys[0], ys[1], ys[2], ys[3]);
        }
        cp_commit();                       // one load group per tile
        if (leader) bulk_commit();         // one store group per tile (may be empty)

        slot  = (slot  + 1 == NBUF) ? 0 : slot  + 1;
        sslot = (sslot + 1 == NBUF) ? 0 : sslot + 1;
        rslot = (rslot + 1 == NBUF) ? 0 : rslot + 1;
    }

    // Epilogue: store the final tile (slot of NTILES-1 == sslot now).
    __syncwarp();
    if (leader) {
        fence_async_shared();
        float* dst = outbase + (size_t)(NTILES - 1) * (SEG * 4);
        for (int i = 0; i < nrows; i++) {
            uint32_t ssrc = (uint32_t)__cvta_generic_to_shared(&tile[sslot][i][0]);
            bulk_s2g(dst + (size_t)i * T_LEN, ssrc, ROW_BYTES);
        }
        bulk_commit();
        bulk_wait_all();                   // all bulk stores complete before exit
    }
}

extern "C" void kernel_launch(void* const* d_in, const int* in_sizes, int n_in,
                              void* d_out, int out_size)
{
    const float* x   = (const float*)d_in[0];
    const float* n   = (const float*)d_in[1];
    const float* a_x = (const float*)d_in[2];
    const float* b_x = (const float*)d_in[3];
    const float* a_n = (const float*)d_in[4];
    const float* b_n = (const float*)d_in[5];
    float* out = (float*)d_out;

    biquad_cascade_kernel<<<2 * XBLOCKS, 32>>>(x, n, a_x, b_x, a_n, b_n, out);
}